// round 4
// baseline (speedup 1.0000x reference)
#include <cuda_runtime.h>

#define IMG_W 1280
#define IMG_H 1024
#define IMG_B 8
#define N_CH  3

#define TOTAL_PX (IMG_B * IMG_H * IMG_W)   // 10,485,760
#define HALF_PX  (TOTAL_PX / 2)            // 5,242,880

__global__ __launch_bounds__(256) void synth_view_kernel(
    const float* __restrict__ img,   // [B,3,H,W]
    const float* __restrict__ disp,  // [B,1,H,W]
    const float* __restrict__ sK,    // [B,4,4]
    const float* __restrict__ tK,    // [B,4,4]
    const float* __restrict__ tv,    // [B,3]
    float* __restrict__ out)         // [B,3,H,W]
{
    int t = blockIdx.x * blockDim.x + threadIdx.x;
    if (t >= HALF_PX) return;

    const float MIN_DISP = 1.0f / 255.0f;
    const float MAX_DISP = 1.0f / 10.0f;
    const float DRANGE   = MAX_DISP - MIN_DISP;
    const float SXW = (float)IMG_W / (float)(IMG_W - 1);
    const float SYH = (float)IMG_H / (float)(IMG_H - 1);
    const long long plane = (long long)IMG_H * IMG_W;

    // per-pixel state for the 2 pixels this thread owns
    int       i00[2], i01[2], i10[2], i11[2];
    float     wxv[2], wyv[2];
    long long imgb[2], outp[2];

#pragma unroll
    for (int k = 0; k < 2; k++) {
        int p   = t + k * HALF_PX;
        int b   = p / (IMG_H * IMG_W);
        int rem = p - b * (IMG_H * IMG_W);
        int y   = rem / IMG_W;
        int x   = rem - y * IMG_W;

        // ---- per-batch folded camera coefficients ----
        const float* sk = sK + b * 16;
        const float* tk = tK + b * 16;
        float fxs = __ldg(sk + 0), cxs = __ldg(sk + 2);
        float fys = __ldg(sk + 5), cys = __ldg(sk + 6);
        float fxt = __ldg(tk + 0), cxt = __ldg(tk + 2);
        float fyt = __ldg(tk + 5), cyt = __ldg(tk + 6);
        float tx = __ldg(tv + b * 3 + 0);
        float ty = __ldg(tv + b * 3 + 1);
        float tz = __ldg(tv + b * 3 + 2);

        float ia = 1.0f / fxs, ic = -cxs / fxs;
        float ie = 1.0f / fys, iff = -cys / fys;
        float Ax = fxt * ia,  Bx = fxt * ic + cxt,  Cx = fxt * tx + cxt * tz;
        float Ay = fyt * ie,  By = fyt * iff + cyt, Cy = fyt * ty + cyt * tz;

        float d     = __ldg(disp + p);              // coalesced: lanes consecutive
        float sd    = MIN_DISP + DRANGE * d;
        float depth = 1.0f / sd;
        float z     = depth + tz;
        float invz  = 1.0f / (z + 1e-7f);
        float u = depth * (Ax * (float)x + Bx) + Cx;
        float v = depth * (Ay * (float)y + By) + Cy;
        float xs = u * invz * SXW - 0.5f;
        float ys = v * invz * SYH - 0.5f;

        float x0f = floorf(xs), y0f = floorf(ys);
        wxv[k] = xs - x0f;          // weights from UNclamped floor (border mode)
        wyv[k] = ys - y0f;

        int x0 = (int)fminf(fmaxf(x0f,        0.0f), (float)(IMG_W - 1));
        int x1 = (int)fminf(fmaxf(x0f + 1.0f, 0.0f), (float)(IMG_W - 1));
        int y0 = (int)fminf(fmaxf(y0f,        0.0f), (float)(IMG_H - 1));
        int y1 = (int)fminf(fmaxf(y0f + 1.0f, 0.0f), (float)(IMG_H - 1));

        i00[k] = y0 * IMG_W + x0;
        i01[k] = y0 * IMG_W + x1;
        i10[k] = y1 * IMG_W + x0;
        i11[k] = y1 * IMG_W + x1;

        imgb[k] = (long long)b * N_CH * plane;
        outp[k] = imgb[k] + (long long)y * IMG_W + x;
    }

#pragma unroll
    for (int ch = 0; ch < N_CH; ch++) {
        float res[2];
#pragma unroll
        for (int k = 0; k < 2; k++) {
            const float* im = img + imgb[k] + (long long)ch * plane;
            float v00 = __ldg(im + i00[k]);
            float v01 = __ldg(im + i01[k]);
            float v10 = __ldg(im + i10[k]);
            float v11 = __ldg(im + i11[k]);
            float wx = wxv[k], wy = wyv[k];
            float omx = 1.0f - wx, omy = 1.0f - wy;
            res[k] = v00 * omx * omy + v01 * wx * omy
                   + v10 * omx * wy  + v11 * wx * wy;
        }
#pragma unroll
        for (int k = 0; k < 2; k++)
            out[outp[k] + (long long)ch * plane] = res[k];   // coalesced scalar store
    }
}

extern "C" void kernel_launch(void* const* d_in, const int* in_sizes, int n_in,
                              void* d_out, int out_size) {
    const float* img  = (const float*)d_in[0];
    const float* disp = (const float*)d_in[1];
    const float* sK   = (const float*)d_in[2];
    const float* tK   = (const float*)d_in[3];
    const float* tv   = (const float*)d_in[4];
    float* out = (float*)d_out;

    int block = 256;
    int grid  = (HALF_PX + block - 1) / block;   // 20,480 blocks
    synth_view_kernel<<<grid, block>>>(img, disp, sK, tK, tv, out);
}

// round 5
// speedup vs baseline: 1.6121x; 1.6121x over previous
#include <cuda_runtime.h>

#define IMG_W 1280
#define IMG_H 1024
#define IMG_B 8
#define N_CH  3

#define PLANE   (IMG_H * IMG_W)          // 1,310,720
#define ROWS_Q  (IMG_H / 4)              // 256 rows per k-slice
#define NTHREADS_TOTAL (IMG_B * ROWS_Q * IMG_W)   // 2,621,440

__global__ __launch_bounds__(256) void synth_view_kernel(
    const float* __restrict__ img,   // [B,3,H,W]
    const float* __restrict__ disp,  // [B,1,H,W]
    const float* __restrict__ sK,    // [B,4,4]
    const float* __restrict__ tK,    // [B,4,4]
    const float* __restrict__ tv,    // [B,3]
    float* __restrict__ out)         // [B,3,H,W]
{
    int t = blockIdx.x * blockDim.x + threadIdx.x;
    if (t >= NTHREADS_TOTAL) return;

    // t -> (b, yb, x) with lanes consecutive in x
    int b   = t / (ROWS_Q * IMG_W);
    int rem = t - b * (ROWS_Q * IMG_W);
    int yb  = rem / IMG_W;               // 0..255
    int x   = rem - yb * IMG_W;

    // ---- per-batch folded camera coefficients (ONCE per thread) ----
    const float* sk = sK + b * 16;
    const float* tk = tK + b * 16;
    float fxs = __ldg(sk + 0), cxs = __ldg(sk + 2);
    float fys = __ldg(sk + 5), cys = __ldg(sk + 6);
    float fxt = __ldg(tk + 0), cxt = __ldg(tk + 2);
    float fyt = __ldg(tk + 5), cyt = __ldg(tk + 6);
    float tx = __ldg(tv + b * 3 + 0);
    float ty = __ldg(tv + b * 3 + 1);
    float tz = __ldg(tv + b * 3 + 2);

    float ia  = __frcp_rn(fxs);
    float ie  = __frcp_rn(fys);
    float Ax  = fxt * ia;
    float Bx  = fmaf(-fxt * cxs, ia, cxt);
    float Cx  = fmaf(fxt, tx, cxt * tz);
    float Ay  = fyt * ie;
    float By  = fmaf(-fyt * cys, ie, cyt);
    float Cy  = fmaf(fyt, ty, cyt * tz);

    const float MIN_DISP = 1.0f / 255.0f;
    const float MAX_DISP = 1.0f / 10.0f;
    const float DRANGE   = MAX_DISP - MIN_DISP;
    const float SXW = (float)IMG_W / (float)(IMG_W - 1);
    const float SYH = (float)IMG_H / (float)(IMG_H - 1);

    float xf = (float)x;
    float ux = fmaf(Ax, xf, Bx);         // x-part, shared by all 4 rows

    int disp_base = b * PLANE + yb * IMG_W + x;     // row k at + k*ROWS_Q*IMG_W
    int img_base  = b * (N_CH * PLANE);

    int   i00[4], i01[4], i10[4], i11[4];
    float wxv[4], wyv[4];

#pragma unroll
    for (int k = 0; k < 4; k++) {
        int   y  = yb + k * ROWS_Q;
        float d  = __ldg(disp + disp_base + k * (ROWS_Q * IMG_W));   // coalesced

        float sd    = fmaf(DRANGE, d, MIN_DISP);
        float depth = __frcp_rn(sd);
        float invz  = __frcp_rn(depth + tz + 1e-7f);

        float u  = fmaf(depth, ux, Cx);
        float v  = fmaf(depth, fmaf(Ay, (float)y, By), Cy);
        float xs = fmaf(u * invz, SXW, -0.5f);
        float ys = fmaf(v * invz, SYH, -0.5f);

        float x0f = floorf(xs), y0f = floorf(ys);
        wxv[k] = xs - x0f;               // weights from UNclamped floor (border mode)
        wyv[k] = ys - y0f;

        int x0 = (int)fminf(fmaxf(x0f,        0.0f), (float)(IMG_W - 1));
        int x1 = (int)fminf(fmaxf(x0f + 1.0f, 0.0f), (float)(IMG_W - 1));
        int y0 = (int)fminf(fmaxf(y0f,        0.0f), (float)(IMG_H - 1));
        int y1 = (int)fminf(fmaxf(y0f + 1.0f, 0.0f), (float)(IMG_H - 1));

        int r0 = y0 * IMG_W, r1 = y1 * IMG_W;
        i00[k] = r0 + x0;  i01[k] = r0 + x1;
        i10[k] = r1 + x0;  i11[k] = r1 + x1;
    }

    int out_base = img_base + yb * IMG_W + x;

#pragma unroll
    for (int ch = 0; ch < N_CH; ch++) {
        const float* im = img + img_base + ch * PLANE;
        float res[4];
#pragma unroll
        for (int k = 0; k < 4; k++) {
            float v00 = __ldg(im + i00[k]);
            float v01 = __ldg(im + i01[k]);
            float v10 = __ldg(im + i10[k]);
            float v11 = __ldg(im + i11[k]);
            float wx = wxv[k], wy = wyv[k];
            float top = fmaf(v01 - v00, wx, v00);
            float bot = fmaf(v11 - v10, wx, v10);
            res[k] = fmaf(bot - top, wy, top);
        }
#pragma unroll
        for (int k = 0; k < 4; k++)
            out[out_base + ch * PLANE + k * (ROWS_Q * IMG_W)] = res[k];  // coalesced
    }
}

extern "C" void kernel_launch(void* const* d_in, const int* in_sizes, int n_in,
                              void* d_out, int out_size) {
    const float* img  = (const float*)d_in[0];
    const float* disp = (const float*)d_in[1];
    const float* sK   = (const float*)d_in[2];
    const float* tK   = (const float*)d_in[3];
    const float* tv   = (const float*)d_in[4];
    float* out = (float*)d_out;

    int block = 256;
    int grid  = (NTHREADS_TOTAL + block - 1) / block;   // 10,240 blocks
    synth_view_kernel<<<grid, block>>>(img, disp, sK, tK, tv, out);
}

// round 6
// speedup vs baseline: 1.7635x; 1.0939x over previous
#include <cuda_runtime.h>

#define IMG_W 1280
#define IMG_H 1024
#define IMG_B 8
#define N_CH  3

#define PLANE   (IMG_H * IMG_W)          // 1,310,720
#define ROWS_Q  (IMG_H / 4)              // 256 rows per k-slice
#define NTHREADS_TOTAL (IMG_B * ROWS_Q * IMG_W)   // 2,621,440

__global__ __launch_bounds__(256) void synth_view_kernel(
    const float* __restrict__ img,   // [B,3,H,W]
    const float* __restrict__ disp,  // [B,1,H,W]
    const float* __restrict__ sK,    // [B,4,4]
    const float* __restrict__ tK,    // [B,4,4]
    const float* __restrict__ tv,    // [B,3]
    float* __restrict__ out)         // [B,3,H,W]
{
    int t = blockIdx.x * blockDim.x + threadIdx.x;
    if (t >= NTHREADS_TOTAL) return;

    // t -> (b, yb, x) with lanes consecutive in x
    int b   = t / (ROWS_Q * IMG_W);
    int rem = t - b * (ROWS_Q * IMG_W);
    int yb  = rem / IMG_W;               // 0..255
    int x   = rem - yb * IMG_W;

    // ---- per-batch folded camera coefficients (once per thread) ----
    const float* sk = sK + b * 16;
    const float* tk = tK + b * 16;
    float fxs = __ldg(sk + 0), cxs = __ldg(sk + 2);
    float fys = __ldg(sk + 5), cys = __ldg(sk + 6);
    float fxt = __ldg(tk + 0), cxt = __ldg(tk + 2);
    float fyt = __ldg(tk + 5), cyt = __ldg(tk + 6);
    float tx = __ldg(tv + b * 3 + 0);
    float ty = __ldg(tv + b * 3 + 1);
    float tz = __ldg(tv + b * 3 + 2);

    float ia  = __frcp_rn(fxs);
    float ie  = __frcp_rn(fys);
    float Ax  = fxt * ia;
    float Bx  = fmaf(-fxt * cxs, ia, cxt);
    float Cx  = fmaf(fxt, tx, cxt * tz);
    float Ay  = fyt * ie;
    float By  = fmaf(-fyt * cys, ie, cyt);
    float Cy  = fmaf(fyt, ty, cyt * tz);

    const float MIN_DISP = 1.0f / 255.0f;
    const float MAX_DISP = 1.0f / 10.0f;
    const float DRANGE   = MAX_DISP - MIN_DISP;
    const float SXW = (float)IMG_W / (float)(IMG_W - 1);
    const float SYH = (float)IMG_H / (float)(IMG_H - 1);

    float xf = (float)x;
    float ux = fmaf(Ax, xf, Bx);         // x-part, shared by all 4 rows

    int disp_base = b * PLANE + yb * IMG_W + x;     // row k at + k*ROWS_Q*IMG_W
    int img_base  = b * (N_CH * PLANE);

    int   i0[4];                         // single base corner per pixel
    float wxv[4], wyv[4];

#pragma unroll
    for (int k = 0; k < 4; k++) {
        int   y  = yb + k * ROWS_Q;
        float d  = __ldcs(disp + disp_base + k * (ROWS_Q * IMG_W));  // streaming

        float sd    = fmaf(DRANGE, d, MIN_DISP);
        float depth = __frcp_rn(sd);
        float invz  = __frcp_rn(depth + tz + 1e-7f);

        float u  = fmaf(depth, ux, Cx);
        float v  = fmaf(depth, fmaf(Ay, (float)y, By), Cy);
        float xs = fmaf(u * invz, SXW, -0.5f);
        float ys = fmaf(v * invz, SYH, -0.5f);

        // fold border clamp into weights: base in [0,W-2]x[0,H-2], w in [0,1].
        // Exactly matches clamp-index/unclamped-weight reference semantics.
        float x0cf = fminf(fmaxf(floorf(xs), 0.0f), (float)(IMG_W - 2));
        float y0cf = fminf(fmaxf(floorf(ys), 0.0f), (float)(IMG_H - 2));
        wxv[k] = fminf(fmaxf(xs - x0cf, 0.0f), 1.0f);
        wyv[k] = fminf(fmaxf(ys - y0cf, 0.0f), 1.0f);

        i0[k] = (int)y0cf * IMG_W + (int)x0cf;
    }

    int out_base = img_base + yb * IMG_W + x;

#pragma unroll
    for (int ch = 0; ch < N_CH; ch++) {
        const float* im = img + img_base + ch * PLANE;
        float res[4];
#pragma unroll
        for (int k = 0; k < 4; k++) {
            const float* p = im + i0[k];
            float v00 = __ldg(p);
            float v01 = __ldg(p + 1);
            float v10 = __ldg(p + IMG_W);
            float v11 = __ldg(p + IMG_W + 1);
            float wx = wxv[k], wy = wyv[k];
            float top = fmaf(v01 - v00, wx, v00);
            float bot = fmaf(v11 - v10, wx, v10);
            res[k] = fmaf(bot - top, wy, top);
        }
#pragma unroll
        for (int k = 0; k < 4; k++)
            __stcs(out + out_base + ch * PLANE + k * (ROWS_Q * IMG_W), res[k]);  // streaming
    }
}

extern "C" void kernel_launch(void* const* d_in, const int* in_sizes, int n_in,
                              void* d_out, int out_size) {
    const float* img  = (const float*)d_in[0];
    const float* disp = (const float*)d_in[1];
    const float* sK   = (const float*)d_in[2];
    const float* tK   = (const float*)d_in[3];
    const float* tv   = (const float*)d_in[4];
    float* out = (float*)d_out;

    int block = 256;
    int grid  = (NTHREADS_TOTAL + block - 1) / block;   // 10,240 blocks
    synth_view_kernel<<<grid, block>>>(img, disp, sK, tK, tv, out);
}

// round 7
// speedup vs baseline: 1.7642x; 1.0004x over previous
#include <cuda_runtime.h>

#define IMG_W 1280
#define IMG_H 1024
#define IMG_B 8
#define N_CH  3

#define PLANE   (IMG_H * IMG_W)          // 1,310,720
#define NPX     8                        // pixels per thread
#define ROWS_O  (IMG_H / NPX)            // 128 rows per k-slice
#define SLICE   (ROWS_O * IMG_W)         // stride between k-slices
#define NTHREADS_TOTAL (IMG_B * ROWS_O * IMG_W)   // 1,310,720

__global__ __launch_bounds__(256) void synth_view_kernel(
    const float* __restrict__ img,   // [B,3,H,W]
    const float* __restrict__ disp,  // [B,1,H,W]
    const float* __restrict__ sK,    // [B,4,4]
    const float* __restrict__ tK,    // [B,4,4]
    const float* __restrict__ tv,    // [B,3]
    float* __restrict__ out)         // [B,3,H,W]
{
    int t = blockIdx.x * blockDim.x + threadIdx.x;
    if (t >= NTHREADS_TOTAL) return;

    // t -> (b, yb, x) with lanes consecutive in x
    int b   = t / SLICE;
    int rem = t - b * SLICE;
    int yb  = rem / IMG_W;               // 0..127
    int x   = rem - yb * IMG_W;

    // ---- per-batch folded camera coefficients (once per thread) ----
    const float* sk = sK + b * 16;
    const float* tk = tK + b * 16;
    float fxs = __ldg(sk + 0), cxs = __ldg(sk + 2);
    float fys = __ldg(sk + 5), cys = __ldg(sk + 6);
    float fxt = __ldg(tk + 0), cxt = __ldg(tk + 2);
    float fyt = __ldg(tk + 5), cyt = __ldg(tk + 6);
    float tx = __ldg(tv + b * 3 + 0);
    float ty = __ldg(tv + b * 3 + 1);
    float tz = __ldg(tv + b * 3 + 2);

    float ia  = __frcp_rn(fxs);
    float ie  = __frcp_rn(fys);
    float Ax  = fxt * ia;
    float Bx  = fmaf(-fxt * cxs, ia, cxt);
    float Cx  = fmaf(fxt, tx, cxt * tz);
    float Ay  = fyt * ie;
    float By  = fmaf(-fyt * cys, ie, cyt);
    float Cy  = fmaf(fyt, ty, cyt * tz);

    const float MIN_DISP = 1.0f / 255.0f;
    const float MAX_DISP = 1.0f / 10.0f;
    const float DRANGE   = MAX_DISP - MIN_DISP;
    const float SXW = (float)IMG_W / (float)(IMG_W - 1);
    const float SYH = (float)IMG_H / (float)(IMG_H - 1);

    float ux = fmaf(Ax, (float)x, Bx);   // x-part, shared by all 8 rows

    int disp_base = b * PLANE + yb * IMG_W + x;     // row k at + k*SLICE
    int img_base  = b * (N_CH * PLANE);

    // batch all 8 disp loads first (independent -> deep MLP)
    float dv[NPX];
#pragma unroll
    for (int k = 0; k < NPX; k++)
        dv[k] = __ldcs(disp + disp_base + k * SLICE);

    int   i0[NPX];
    float wxv[NPX], wyv[NPX];

#pragma unroll
    for (int k = 0; k < NPX; k++) {
        int   y  = yb + k * ROWS_O;

        float sd    = fmaf(DRANGE, dv[k], MIN_DISP);
        float depth = __frcp_rn(sd);
        float invz  = __frcp_rn(depth + tz + 1e-7f);

        float u  = fmaf(depth, ux, Cx);
        float v  = fmaf(depth, fmaf(Ay, (float)y, By), Cy);
        float xs = fmaf(u * invz, SXW, -0.5f);
        float ys = fmaf(v * invz, SYH, -0.5f);

        // border clamp folded into weights: base in [0,W-2]x[0,H-2], w in [0,1]
        float x0cf = fminf(fmaxf(floorf(xs), 0.0f), (float)(IMG_W - 2));
        float y0cf = fminf(fmaxf(floorf(ys), 0.0f), (float)(IMG_H - 2));
        wxv[k] = fminf(fmaxf(xs - x0cf, 0.0f), 1.0f);
        wyv[k] = fminf(fmaxf(ys - y0cf, 0.0f), 1.0f);

        i0[k] = (int)y0cf * IMG_W + (int)x0cf;
    }

    int out_base = img_base + yb * IMG_W + x;

#pragma unroll
    for (int ch = 0; ch < N_CH; ch++) {
        const float* im = img + img_base + ch * PLANE;
        float res[NPX];
#pragma unroll
        for (int k = 0; k < NPX; k++) {
            const float* p = im + i0[k];
            float v00 = __ldg(p);
            float v01 = __ldg(p + 1);
            float v10 = __ldg(p + IMG_W);
            float v11 = __ldg(p + IMG_W + 1);
            float wx = wxv[k], wy = wyv[k];
            float top = fmaf(v01 - v00, wx, v00);
            float bot = fmaf(v11 - v10, wx, v10);
            res[k] = fmaf(bot - top, wy, top);
        }
#pragma unroll
        for (int k = 0; k < NPX; k++)
            __stcs(out + out_base + ch * PLANE + k * SLICE, res[k]);  // streaming
    }
}

extern "C" void kernel_launch(void* const* d_in, const int* in_sizes, int n_in,
                              void* d_out, int out_size) {
    const float* img  = (const float*)d_in[0];
    const float* disp = (const float*)d_in[1];
    const float* sK   = (const float*)d_in[2];
    const float* tK   = (const float*)d_in[3];
    const float* tv   = (const float*)d_in[4];
    float* out = (float*)d_out;

    int block = 256;
    int grid  = (NTHREADS_TOTAL + block - 1) / block;   // 5,120 blocks
    synth_view_kernel<<<grid, block>>>(img, disp, sK, tK, tv, out);
}

// round 8
// speedup vs baseline: 1.7850x; 1.0118x over previous
#include <cuda_runtime.h>

#define IMG_W 1280
#define IMG_H 1024
#define IMG_B 8
#define N_CH  3

#define PLANE   (IMG_H * IMG_W)      // 1,310,720
#define ROWS_Q  (IMG_H / 4)          // 256 rows per k-slice (4 px/thread over rows)
#define CHUNK   256                  // x-pixels per block
#define XCHUNKS (IMG_W / CHUNK)      // 5
#define NBLOCKS (IMG_B * ROWS_Q * XCHUNKS)   // 10,240

__global__ __launch_bounds__(256) void synth_view_kernel(
    const float* __restrict__ img,   // [B,3,H,W]
    const float* __restrict__ disp,  // [B,1,H,W]
    const float* __restrict__ sK,    // [B,4,4]
    const float* __restrict__ tK,    // [B,4,4]
    const float* __restrict__ tv,    // [B,3]
    float* __restrict__ out)         // [B,3,H,W]
{
    __shared__ int   i0A[4 * CHUNK];     // [k][x]
    __shared__ float wxA[4 * CHUNK];
    __shared__ float wyA[4 * CHUNK];
    __shared__ float resA[12 * CHUNK];   // [(ch*4+k)][x]

    const int tid = threadIdx.x;
    int blk = blockIdx.x;
    int b   = blk / (ROWS_Q * XCHUNKS);
    int rem = blk - b * (ROWS_Q * XCHUNKS);
    int yb  = rem / XCHUNKS;
    int xbase = (rem - yb * XCHUNKS) * CHUNK;

    const int img_base = b * (N_CH * PLANE);

    // ================= Phase A: disp float4 load + coords -> smem =================
    {
        // per-batch folded camera coefficients
        const float* sk = sK + b * 16;
        const float* tk = tK + b * 16;
        float fxs = __ldg(sk + 0), cxs = __ldg(sk + 2);
        float fys = __ldg(sk + 5), cys = __ldg(sk + 6);
        float fxt = __ldg(tk + 0), cxt = __ldg(tk + 2);
        float fyt = __ldg(tk + 5), cyt = __ldg(tk + 6);
        float tx = __ldg(tv + b * 3 + 0);
        float ty = __ldg(tv + b * 3 + 1);
        float tz = __ldg(tv + b * 3 + 2);

        float ia  = __frcp_rn(fxs);
        float ie  = __frcp_rn(fys);
        float Ax  = fxt * ia;
        float Bx  = fmaf(-fxt * cxs, ia, cxt);
        float Cx  = fmaf(fxt, tx, cxt * tz);
        float Ay  = fyt * ie;
        float By  = fmaf(-fyt * cys, ie, cyt);
        float Cy  = fmaf(fyt, ty, cyt * tz);

        const float MIN_DISP = 1.0f / 255.0f;
        const float MAX_DISP = 1.0f / 10.0f;
        const float DRANGE   = MAX_DISP - MIN_DISP;
        const float SXW = (float)IMG_W / (float)(IMG_W - 1);
        const float SYH = (float)IMG_H / (float)(IMG_H - 1);

        int k   = tid >> 6;          // 0..3 (k-slice)
        int q   = tid & 63;          // quad within chunk
        int y   = yb + k * ROWS_Q;
        int xq  = xbase + q * 4;

        float4 d4 = __ldcs(reinterpret_cast<const float4*>(
                           disp + b * PLANE + y * IMG_W + xq));
        float dv[4] = {d4.x, d4.y, d4.z, d4.w};

        float vy = fmaf(Ay, (float)y, By);

        int   i0v[4];
        float wxv[4], wyv[4];
#pragma unroll
        for (int i = 0; i < 4; i++) {
            float sd    = fmaf(DRANGE, dv[i], MIN_DISP);
            float depth = __frcp_rn(sd);
            float invz  = __frcp_rn(depth + tz + 1e-7f);

            float u  = fmaf(depth, fmaf(Ax, (float)(xq + i), Bx), Cx);
            float v  = fmaf(depth, vy, Cy);
            float xs = fmaf(u * invz, SXW, -0.5f);
            float ys = fmaf(v * invz, SYH, -0.5f);

            // border clamp folded into weights (exactly matches reference)
            float x0cf = fminf(fmaxf(floorf(xs), 0.0f), (float)(IMG_W - 2));
            float y0cf = fminf(fmaxf(floorf(ys), 0.0f), (float)(IMG_H - 2));
            wxv[i] = fminf(fmaxf(xs - x0cf, 0.0f), 1.0f);
            wyv[i] = fminf(fmaxf(ys - y0cf, 0.0f), 1.0f);
            i0v[i] = (int)y0cf * IMG_W + (int)x0cf;
        }
        int base = k * CHUNK + q * 4;
        *reinterpret_cast<int4*>  (&i0A[base]) = make_int4(i0v[0], i0v[1], i0v[2], i0v[3]);
        *reinterpret_cast<float4*>(&wxA[base]) = make_float4(wxv[0], wxv[1], wxv[2], wxv[3]);
        *reinterpret_cast<float4*>(&wyA[base]) = make_float4(wyv[0], wyv[1], wyv[2], wyv[3]);
    }
    __syncthreads();

    // ================= Phase B: lane-consecutive gathers =================
    {
        int   ci[4];
        float cwx[4], cwy[4];
#pragma unroll
        for (int k = 0; k < 4; k++) {
            ci[k]  = i0A[k * CHUNK + tid];
            cwx[k] = wxA[k * CHUNK + tid];
            cwy[k] = wyA[k * CHUNK + tid];
        }
#pragma unroll
        for (int ch = 0; ch < N_CH; ch++) {
            const float* im = img + img_base + ch * PLANE;
            float v00[4], v01[4], v10[4], v11[4];
#pragma unroll
            for (int k = 0; k < 4; k++) {
                const float* p = im + ci[k];
                v00[k] = __ldg(p);
                v01[k] = __ldg(p + 1);
                v10[k] = __ldg(p + IMG_W);
                v11[k] = __ldg(p + IMG_W + 1);
            }
#pragma unroll
            for (int k = 0; k < 4; k++) {
                float wx = cwx[k], wy = cwy[k];
                float top = fmaf(v01[k] - v00[k], wx, v00[k]);
                float bot = fmaf(v11[k] - v10[k], wx, v10[k]);
                resA[(ch * 4 + k) * CHUNK + tid] = fmaf(bot - top, wy, top);
            }
        }
    }
    __syncthreads();

    // ================= Phase C: float4 stores =================
#pragma unroll
    for (int j = 0; j < 3; j++) {
        int lin   = j * CHUNK + tid;     // 0..767
        int plane = lin >> 6;            // 0..11 = ch*4 + k
        int q2    = lin & 63;
        int ch    = plane >> 2;
        int kk    = plane & 3;
        float4 r = *reinterpret_cast<float4*>(&resA[plane * CHUNK + q2 * 4]);
        __stcs(reinterpret_cast<float4*>(
                   out + img_base + ch * PLANE + (yb + kk * ROWS_Q) * IMG_W
                       + xbase + q2 * 4),
               r);
    }
}

extern "C" void kernel_launch(void* const* d_in, const int* in_sizes, int n_in,
                              void* d_out, int out_size) {
    const float* img  = (const float*)d_in[0];
    const float* disp = (const float*)d_in[1];
    const float* sK   = (const float*)d_in[2];
    const float* tK   = (const float*)d_in[3];
    const float* tv   = (const float*)d_in[4];
    float* out = (float*)d_out;

    synth_view_kernel<<<NBLOCKS, 256>>>(img, disp, sK, tK, tv, out);
}

// round 9
// speedup vs baseline: 2.1771x; 1.2197x over previous
#include <cuda_runtime.h>

#define IMG_W 1280
#define IMG_H 1024
#define IMG_B 8
#define N_CH  3

#define PLANE   (IMG_H * IMG_W)          // 1,310,720
#define YGRPS   (IMG_H / 4)              // 256 groups of 4 ADJACENT rows
#define NTHREADS_TOTAL (IMG_B * YGRPS * IMG_W)   // 2,621,440

__global__ __launch_bounds__(256) void synth_view_kernel(
    const float* __restrict__ img,   // [B,3,H,W]
    const float* __restrict__ disp,  // [B,1,H,W]
    const float* __restrict__ sK,    // [B,4,4]
    const float* __restrict__ tK,    // [B,4,4]
    const float* __restrict__ tv,    // [B,3]
    float* __restrict__ out)         // [B,3,H,W]
{
    int t = blockIdx.x * blockDim.x + threadIdx.x;
    if (t >= NTHREADS_TOTAL) return;

    // t -> (b, yg, x): lanes consecutive in x; thread owns 4 ADJACENT rows
    int b   = t / (YGRPS * IMG_W);
    int rem = t - b * (YGRPS * IMG_W);
    int yg  = rem / IMG_W;               // 0..255
    int x   = rem - yg * IMG_W;
    int y0r = yg * 4;                    // first of 4 adjacent rows

    // ---- per-batch folded camera coefficients (once per thread) ----
    const float* sk = sK + b * 16;
    const float* tk = tK + b * 16;
    float fxs = __ldg(sk + 0), cxs = __ldg(sk + 2);
    float fys = __ldg(sk + 5), cys = __ldg(sk + 6);
    float fxt = __ldg(tk + 0), cxt = __ldg(tk + 2);
    float fyt = __ldg(tk + 5), cyt = __ldg(tk + 6);
    float tx = __ldg(tv + b * 3 + 0);
    float ty = __ldg(tv + b * 3 + 1);
    float tz = __ldg(tv + b * 3 + 2);

    float ia  = __frcp_rn(fxs);
    float ie  = __frcp_rn(fys);
    float Ax  = fxt * ia;
    float Bx  = fmaf(-fxt * cxs, ia, cxt);
    float Cx  = fmaf(fxt, tx, cxt * tz);
    float Ay  = fyt * ie;
    float By  = fmaf(-fyt * cys, ie, cyt);
    float Cy  = fmaf(fyt, ty, cyt * tz);

    const float MIN_DISP = 1.0f / 255.0f;
    const float MAX_DISP = 1.0f / 10.0f;
    const float DRANGE   = MAX_DISP - MIN_DISP;
    const float SXW = (float)IMG_W / (float)(IMG_W - 1);
    const float SYH = (float)IMG_H / (float)(IMG_H - 1);

    float ux = fmaf(Ax, (float)x, Bx);   // x-part, shared by all 4 rows

    int disp_base = b * PLANE + y0r * IMG_W + x;   // row k at + k*IMG_W
    int img_base  = b * (N_CH * PLANE);

    // batch the 4 disp loads (coalesced per row)
    float dv[4];
#pragma unroll
    for (int k = 0; k < 4; k++)
        dv[k] = __ldcs(disp + disp_base + k * IMG_W);

    int   i0[4];
    float wxv[4], wyv[4];

#pragma unroll
    for (int k = 0; k < 4; k++) {
        int   y  = y0r + k;

        float sd    = fmaf(DRANGE, dv[k], MIN_DISP);
        float depth = __frcp_rn(sd);
        float invz  = __frcp_rn(depth + tz + 1e-7f);

        float u  = fmaf(depth, ux, Cx);
        float v  = fmaf(depth, fmaf(Ay, (float)y, By), Cy);
        float xs = fmaf(u * invz, SXW, -0.5f);
        float ys = fmaf(v * invz, SYH, -0.5f);

        // border clamp folded into weights: base in [0,W-2]x[0,H-2], w in [0,1]
        // (exactly matches clamp-index/unclamped-weight reference semantics)
        float x0cf = fminf(fmaxf(floorf(xs), 0.0f), (float)(IMG_W - 2));
        float y0cf = fminf(fmaxf(floorf(ys), 0.0f), (float)(IMG_H - 2));
        wxv[k] = fminf(fmaxf(xs - x0cf, 0.0f), 1.0f);
        wyv[k] = fminf(fmaxf(ys - y0cf, 0.0f), 1.0f);

        i0[k] = (int)y0cf * IMG_W + (int)x0cf;
    }

    int out_base = img_base + y0r * IMG_W + x;

#pragma unroll
    for (int ch = 0; ch < N_CH; ch++) {
        const float* im = img + img_base + ch * PLANE;
        float res[4];
#pragma unroll
        for (int k = 0; k < 4; k++) {
            const float* p = im + i0[k];
            float v00 = __ldg(p);
            float v01 = __ldg(p + 1);
            float v10 = __ldg(p + IMG_W);
            float v11 = __ldg(p + IMG_W + 1);
            float wx = wxv[k], wy = wyv[k];
            float top = fmaf(v01 - v00, wx, v00);
            float bot = fmaf(v11 - v10, wx, v10);
            res[k] = fmaf(bot - top, wy, top);
        }
#pragma unroll
        for (int k = 0; k < 4; k++)
            __stcs(out + out_base + ch * PLANE + k * IMG_W, res[k]);  // coalesced
    }
}

extern "C" void kernel_launch(void* const* d_in, const int* in_sizes, int n_in,
                              void* d_out, int out_size) {
    const float* img  = (const float*)d_in[0];
    const float* disp = (const float*)d_in[1];
    const float* sK   = (const float*)d_in[2];
    const float* tK   = (const float*)d_in[3];
    const float* tv   = (const float*)d_in[4];
    float* out = (float*)d_out;

    int block = 256;
    int grid  = (NTHREADS_TOTAL + block - 1) / block;   // 10,240 blocks
    synth_view_kernel<<<grid, block>>>(img, disp, sK, tK, tv, out);
}